// round 1
// baseline (speedup 1.0000x reference)
#include <cuda_runtime.h>
#include <math.h>

// ---------------- problem constants ----------------
#define BB   16
#define CC   256
#define HH   56
#define WW_  56
#define HWSZ 3136            // 56*56
#define WH   7
#define WWIN 7
#define NN   49              // window size
#define MM   1024            // B * 8 * 8 windows
#define NHD  8
#define HDD  32
#define HID_ 1024
#define EPSV 1e-5f

// ---------------- device scratch (no allocation allowed) ----------------
__device__ float g_xf  [(size_t)MM * CC * NN];          //  51.4 MB
__device__ float g_qkv [(size_t)MM * 3 * CC * NN];      // 154.1 MB
__device__ float g_o   [(size_t)MM * CC * NN];          //  51.4 MB
__device__ float g_y1  [(size_t)MM * CC * NN];          //  51.4 MB
__device__ float g_bias[NHD * NN * NN];                 //  77 KB
__device__ float g_ln2 [(size_t)BB * CC * HWSZ];        //  51.4 MB
__device__ float g_hid [(size_t)BB * HID_ * HWSZ];      // 205.5 MB

// ---------------- relative-position bias precompute ----------------
__global__ void k_bias(const float* __restrict__ table, float* __restrict__ bias) {
    int i = blockIdx.x * blockDim.x + threadIdx.x;
    if (i >= NHD * NN * NN) return;
    int h = i / (NN * NN);
    int rem = i % (NN * NN);
    int n = rem / NN, k = rem % NN;
    int dr = n / WWIN - k / WWIN + (WH - 1);
    int dc = n % WWIN - k % WWIN + (WWIN - 1);
    bias[i] = table[(dr * (2 * WWIN - 1) + dc) * NHD + h];
}

// ---------------- channel LayerNorm (NCHW), optionally writing blocked layout ----------------
// grid: B*H*2  (w tiles of 28), block: (28, 8)
template <bool BLOCKED>
__global__ void k_ln(const float* __restrict__ x, const float* __restrict__ w,
                     const float* __restrict__ b, float* __restrict__ out) {
    int blk = blockIdx.x;
    int w0  = (blk & 1) * 28;
    int bh  = blk >> 1;
    int h   = bh % HH;
    int bb  = bh / HH;
    int tx = threadIdx.x;   // 0..27
    int ty = threadIdx.y;   // 0..7
    int wpos = w0 + tx;

    const float* xb = x + (size_t)bb * CC * HWSZ + h * WW_ + wpos;

    float s = 0.f, s2 = 0.f;
    #pragma unroll
    for (int c = ty; c < CC; c += 8) {
        float v = xb[(size_t)c * HWSZ];
        s += v; s2 += v * v;
    }
    __shared__ float sh_s[8][28], sh_s2[8][28];
    __shared__ float sh_mu[28], sh_rs[28];
    sh_s[ty][tx] = s; sh_s2[ty][tx] = s2;
    __syncthreads();
    if (ty == 0) {
        float ts = 0.f, ts2 = 0.f;
        #pragma unroll
        for (int j = 0; j < 8; j++) { ts += sh_s[j][tx]; ts2 += sh_s2[j][tx]; }
        float mu  = ts * (1.f / CC);
        float var = ts2 * (1.f / CC) - mu * mu;
        sh_mu[tx] = mu;
        sh_rs[tx] = rsqrtf(var + EPSV);
    }
    __syncthreads();
    float mu = sh_mu[tx], rs = sh_rs[tx];

    if (BLOCKED) {
        int m = bb * 64 + (h / WH) * 8 + (wpos / WWIN);
        int n = (h % WH) * WWIN + (wpos % WWIN);
        #pragma unroll
        for (int c = ty; c < CC; c += 8) {
            float v = (xb[(size_t)c * HWSZ] - mu) * rs * w[c] + b[c];
            out[((size_t)m * CC + c) * NN + n] = v;
        }
    } else {
        float* ob = out + (size_t)bb * CC * HWSZ + h * WW_ + wpos;
        #pragma unroll
        for (int c = ty; c < CC; c += 8) {
            float v = (xb[(size_t)c * HWSZ] - mu) * rs * w[c] + b[c];
            ob[(size_t)c * HWSZ] = v;
        }
    }
}

// ---------------- per-window GEMM: out[m][o][n] = W[o][:] . in[m][:][n] + bias[o] ----------------
// IC = 256 fixed.  Tile: 128 output rows x 49 cols.  grid: (OC/128, M), block 256
__global__ void k_wgemm(const float* __restrict__ W, const float* __restrict__ bias,
                        const float* __restrict__ in, float* __restrict__ out, int OC) {
    int m  = blockIdx.y;
    int o0 = blockIdx.x * 128;

    __shared__ float Wt[128][33];
    __shared__ float Xt[32][49];

    const float* inb = in + (size_t)m * CC * NN;
    int tid = threadIdx.x;
    int cg  = tid & 3;          // column group 0..3
    int rp  = tid >> 2;         // row pair 0..63

    float acc0[13], acc1[13];
    #pragma unroll
    for (int j = 0; j < 13; j++) { acc0[j] = 0.f; acc1[j] = 0.f; }

    for (int c0 = 0; c0 < CC; c0 += 32) {
        for (int i = tid; i < 128 * 32; i += 256) {
            int rr = i >> 5, cc = i & 31;
            Wt[rr][cc] = W[(size_t)(o0 + rr) * CC + c0 + cc];
        }
        for (int i = tid; i < 32 * NN; i += 256) {
            int rr = i / NN, cc = i % NN;
            Xt[rr][cc] = inb[(size_t)(c0 + rr) * NN + cc];
        }
        __syncthreads();
        #pragma unroll
        for (int kk = 0; kk < 32; kk++) {
            float w0v = Wt[2 * rp][kk];
            float w1v = Wt[2 * rp + 1][kk];
            #pragma unroll
            for (int j = 0; j < 13; j++) {
                int col = cg + 4 * j;
                if (col < NN) {
                    float xv = Xt[kk][col];
                    acc0[j] += w0v * xv;
                    acc1[j] += w1v * xv;
                }
            }
        }
        __syncthreads();
    }

    int r0 = o0 + 2 * rp;
    float b0 = bias[r0], b1 = bias[r0 + 1];
    float* ob0 = out + ((size_t)m * OC + r0) * NN;
    float* ob1 = ob0 + NN;
    #pragma unroll
    for (int j = 0; j < 13; j++) {
        int col = cg + 4 * j;
        if (col < NN) {
            ob0[col] = acc0[j] + b0;
            ob1[col] = acc1[j] + b1;
        }
    }
}

// ---------------- attention core per (window, head) ----------------
// grid: M*8, block 256
__global__ void k_attn(const float* __restrict__ qkv, const float* __restrict__ bias,
                       float* __restrict__ out) {
    int m = blockIdx.x >> 3;
    int h = blockIdx.x & 7;

    __shared__ float q [HDD * NN];
    __shared__ float kt[HDD * NN];
    __shared__ float v [HDD * NN];
    __shared__ float at[NN * 50];

    int tid = threadIdx.x;
    const float* base = qkv + (size_t)m * (3 * CC) * NN;
    const float* qg = base + (h * HDD) * NN;
    const float* kg = base + (CC + h * HDD) * NN;
    const float* vg = base + (2 * CC + h * HDD) * NN;
    for (int i = tid; i < HDD * NN; i += 256) {
        q[i] = qg[i]; kt[i] = kg[i]; v[i] = vg[i];
    }
    __syncthreads();

    const float* bh = bias + h * NN * NN;
    const float scale = 0.17677669529663687f;   // 32^-0.5
    for (int i = tid; i < NN * NN; i += 256) {
        int n = i / NN, kk = i % NN;
        float s = 0.f;
        #pragma unroll
        for (int d = 0; d < HDD; d++) s += q[d * NN + n] * kt[d * NN + kk];
        at[n * 50 + kk] = s * scale + bh[i];
    }
    __syncthreads();

    int warp = tid >> 5, lane = tid & 31;
    for (int n = warp; n < NN; n += 8) {
        float v0 = at[n * 50 + lane];
        float v1 = (lane + 32 < NN) ? at[n * 50 + lane + 32] : -INFINITY;
        float mx = fmaxf(v0, v1);
        #pragma unroll
        for (int o = 16; o; o >>= 1) mx = fmaxf(mx, __shfl_xor_sync(0xffffffffu, mx, o));
        float e0 = __expf(v0 - mx);
        float e1 = (lane + 32 < NN) ? __expf(v1 - mx) : 0.f;
        float s = e0 + e1;
        #pragma unroll
        for (int o = 16; o; o >>= 1) s += __shfl_xor_sync(0xffffffffu, s, o);
        float inv = 1.f / s;
        at[n * 50 + lane] = e0 * inv;
        if (lane + 32 < NN) at[n * 50 + lane + 32] = e1 * inv;
    }
    __syncthreads();

    float* ob = out + ((size_t)m * CC + h * HDD) * NN;
    for (int i = tid; i < HDD * NN; i += 256) {
        int d = i / NN, n = i % NN;
        float s = 0.f;
        #pragma unroll
        for (int kk = 0; kk < NN; kk++) s += at[n * 50 + kk] * v[d * NN + kk];
        ob[d * NN + n] = s;
    }
}

// ---------------- residual + unblock ----------------
__global__ void k_resid(const float* __restrict__ x, const float* __restrict__ y,
                        float* __restrict__ out) {
    int i = blockIdx.x * blockDim.x + threadIdx.x;
    if (i >= BB * CC * HWSZ) return;
    int w = i % WW_; int t = i / WW_;
    int h = t % HH;  t /= HH;
    int c = t % CC;  int b = t / CC;
    int m = b * 64 + (h / WH) * 8 + (w / WWIN);
    int n = (h % WH) * WWIN + (w % WWIN);
    out[i] = x[i] + y[((size_t)m * CC + c) * NN + n];
}

// ---------------- MLP GEMM (per batch, NCHW with HW flattened) ----------------
// out[b][o][p] = act( W[o][:] . in[b][:][p] + bias[o] )   [optional += into out]
// grid: (HW/64 = 49, OC/64, B), block 256, 64x64 tile, 4x4 register blocking
__global__ void k_mlp(const float* __restrict__ W, const float* __restrict__ bias,
                      const float* __restrict__ in, float* __restrict__ out,
                      int OC, int IC, int do_gelu, int accum) {
    int b  = blockIdx.z;
    int o0 = blockIdx.y * 64;
    int p0 = blockIdx.x * 64;

    __shared__ float Wt[64][33];
    __shared__ float Xt[32][68];

    const float* inb = in + (size_t)b * IC * HWSZ;
    float* ob = out + (size_t)b * OC * HWSZ;

    int tid = threadIdx.x;
    int tx = tid & 15, ty = tid >> 4;

    float acc[4][4];
    #pragma unroll
    for (int i = 0; i < 4; i++)
        #pragma unroll
        for (int j = 0; j < 4; j++) acc[i][j] = 0.f;

    for (int c0 = 0; c0 < IC; c0 += 32) {
        for (int i = tid; i < 64 * 32; i += 256) {
            int rr = i >> 5, cc = i & 31;
            Wt[rr][cc] = W[(size_t)(o0 + rr) * IC + c0 + cc];
        }
        for (int i = tid; i < 32 * 64; i += 256) {
            int rr = i >> 6, cc = i & 63;
            Xt[rr][cc] = inb[(size_t)(c0 + rr) * HWSZ + p0 + cc];
        }
        __syncthreads();
        #pragma unroll
        for (int kk = 0; kk < 32; kk++) {
            float a[4], bv[4];
            #pragma unroll
            for (int i = 0; i < 4; i++) a[i] = Wt[ty * 4 + i][kk];
            #pragma unroll
            for (int j = 0; j < 4; j++) bv[j] = Xt[kk][tx * 4 + j];
            #pragma unroll
            for (int i = 0; i < 4; i++)
                #pragma unroll
                for (int j = 0; j < 4; j++) acc[i][j] += a[i] * bv[j];
        }
        __syncthreads();
    }

    #pragma unroll
    for (int i = 0; i < 4; i++) {
        int o = o0 + ty * 4 + i;
        float bb = bias[o];
        #pragma unroll
        for (int j = 0; j < 4; j++) {
            float vv = acc[i][j] + bb;
            if (do_gelu) vv = 0.5f * vv * (1.f + erff(vv * 0.70710678118654752f));
            size_t idx = (size_t)o * HWSZ + p0 + tx * 4 + j;
            if (accum) ob[idx] += vv; else ob[idx] = vv;
        }
    }
}

// ---------------- host launcher ----------------
extern "C" void kernel_launch(void* const* d_in, const int* in_sizes, int n_in,
                              void* d_out, int out_size) {
    const float* x      = (const float*)d_in[0];
    const float* ln1_w  = (const float*)d_in[1];
    const float* ln1_b  = (const float*)d_in[2];
    const float* ln2_w  = (const float*)d_in[3];
    const float* ln2_b  = (const float*)d_in[4];
    const float* qkv_w  = (const float*)d_in[5];
    const float* qkv_b  = (const float*)d_in[6];
    const float* proj_w = (const float*)d_in[7];
    const float* proj_b = (const float*)d_in[8];
    const float* table  = (const float*)d_in[9];
    const float* fc1_w  = (const float*)d_in[10];
    const float* fc1_b  = (const float*)d_in[11];
    const float* fc2_w  = (const float*)d_in[12];
    const float* fc2_b  = (const float*)d_in[13];
    float* out = (float*)d_out;

    float *p_xf, *p_qkv, *p_o, *p_y1, *p_bias, *p_ln2, *p_hid;
    cudaGetSymbolAddress((void**)&p_xf,  g_xf);
    cudaGetSymbolAddress((void**)&p_qkv, g_qkv);
    cudaGetSymbolAddress((void**)&p_o,   g_o);
    cudaGetSymbolAddress((void**)&p_y1,  g_y1);
    cudaGetSymbolAddress((void**)&p_bias,g_bias);
    cudaGetSymbolAddress((void**)&p_ln2, g_ln2);
    cudaGetSymbolAddress((void**)&p_hid, g_hid);

    // relative-position bias
    k_bias<<<(NHD * NN * NN + 255) / 256, 256>>>(table, p_bias);

    // LN1 + blockify -> g_xf (M, C, N)
    k_ln<true><<<BB * HH * 2, dim3(28, 8)>>>(x, ln1_w, ln1_b, p_xf);

    // attention pass 1
    k_wgemm<<<dim3(6, MM), 256>>>(qkv_w, qkv_b, p_xf, p_qkv, 3 * CC);
    k_attn <<<MM * NHD, 256>>>(p_qkv, p_bias, p_o);
    k_wgemm<<<dim3(2, MM), 256>>>(proj_w, proj_b, p_o, p_y1, CC);

    // attention pass 2 (same weights)
    k_wgemm<<<dim3(6, MM), 256>>>(qkv_w, qkv_b, p_y1, p_qkv, 3 * CC);
    k_attn <<<MM * NHD, 256>>>(p_qkv, p_bias, p_o);
    k_wgemm<<<dim3(2, MM), 256>>>(proj_w, proj_b, p_o, p_xf, CC);

    // residual + unblock -> out
    k_resid<<<(BB * CC * HWSZ + 255) / 256, 256>>>(x, p_xf, out);

    // LN2 (NCHW layout)
    k_ln<false><<<BB * HH * 2, dim3(28, 8)>>>(out, ln2_w, ln2_b, p_ln2);

    // MLP: fc1 + exact GELU, then fc2 accumulated into out
    k_mlp<<<dim3(HWSZ / 64, HID_ / 64, BB), 256>>>(fc1_w, fc1_b, p_ln2, p_hid, HID_, CC, 1, 0);
    k_mlp<<<dim3(HWSZ / 64, CC / 64,  BB), 256>>>(fc2_w, fc2_b, p_hid, out, CC, HID_, 0, 1);
}

// round 3
// speedup vs baseline: 2.4988x; 2.4988x over previous
#include <cuda_runtime.h>
#include <cuda_bf16.h>
#include <math.h>
#include <stdint.h>

// ---------------- problem constants ----------------
#define BB   16
#define CC   256
#define HH   56
#define HWSZ 3136
#define WWIN 7
#define NN   49
#define MM   1024
#define NHD  8
#define HID_ 1024
#define NPTS 50176          // 1024 windows * 49  ==  16 * 3136
#define EPSV 1e-5f

// ---------------- device scratch ----------------
__device__ float g_xf [(size_t)NPTS * CC];        // (pt, C)
__device__ float g_qkv[(size_t)NPTS * 3 * CC];    // (pt, 3C)
__device__ float g_o  [(size_t)NPTS * CC];
__device__ float g_y1 [(size_t)NPTS * CC];
__device__ float g_ln2[(size_t)NPTS * CC];
__device__ float g_hid[(size_t)NPTS * HID_];
__device__ float g_bias[NHD * NN * NN];

// ================= mma.sync helpers =================
__device__ __forceinline__ void mma16816(float* c, const uint32_t* a, const uint32_t* b) {
    asm volatile(
        "mma.sync.aligned.m16n8k16.row.col.f32.bf16.bf16.f32 "
        "{%0,%1,%2,%3}, {%4,%5,%6,%7}, {%8,%9}, {%0,%1,%2,%3};"
        : "+f"(c[0]), "+f"(c[1]), "+f"(c[2]), "+f"(c[3])
        : "r"(a[0]), "r"(a[1]), "r"(a[2]), "r"(a[3]), "r"(b[0]), "r"(b[1]));
}

// split x,y into bf16 hi pair (packed) and bf16 lo pair (packed)
__device__ __forceinline__ uint32_t split2(float x, float y, uint32_t& lo2) {
    __nv_bfloat16 hx = __float2bfloat16(x);
    __nv_bfloat16 hy = __float2bfloat16(y);
    float lx = x - __bfloat162float(hx);
    float ly = y - __bfloat162float(hy);
    __nv_bfloat162 h; h.x = hx; h.y = hy;
    __nv_bfloat162 l; l.x = __float2bfloat16(lx); l.y = __float2bfloat16(ly);
    lo2 = *reinterpret_cast<uint32_t*>(&l);
    return *reinterpret_cast<uint32_t*>(&h);
}

// ================= bf16 split GEMM via mma.sync =================
// out[pt][o] = X[pt,:] . W[o,:] + bias[o]  (optional exact GELU)
// block tile: 128 pt (M) x 128 o (N), K-chunk 32, double-buffered.
#define SPAD  40                    // halves per 32-k row (80B: conflict-free)
#define TILEH (128 * SPAD)          // halves per tile buffer
#define GSMEM (8 * TILEH * 2)       // 4 arrays x 2 buffers, bytes = 81920

__global__ void __launch_bounds__(256, 1)
k_gemm(const float* __restrict__ W, const float* __restrict__ bias,
       const float* __restrict__ X, float* __restrict__ out,
       int IC, int OC, int gelu)
{
    extern __shared__ __align__(16) __nv_bfloat16 sm[];
    __nv_bfloat16* Ahi = sm;                    // X tile  [2][128][SPAD]
    __nv_bfloat16* Alo = Ahi + 2 * TILEH;
    __nv_bfloat16* Bhi = Alo + 2 * TILEH;       // W tile
    __nv_bfloat16* Blo = Bhi + 2 * TILEH;

    const int tid = threadIdx.x, lane = tid & 31, wid = tid >> 5;
    const int p0 = blockIdx.x * 128, o0 = blockIdx.y * 128;
    const int wm = (wid & 1) * 64, wn = (wid >> 1) * 32;
    const int g = lane >> 2, t = lane & 3;
    const int lrow = tid >> 3, lc4 = (tid & 7) << 2;

    float acc[4][4][4];
    #pragma unroll
    for (int i = 0; i < 4; i++)
        #pragma unroll
        for (int j = 0; j < 4; j++)
            #pragma unroll
            for (int q = 0; q < 4; q++) acc[i][j][q] = 0.f;

    float4 ra[4], rb[4];

    auto fetch = [&](int kt) {
        int c0 = kt * 32;
        #pragma unroll
        for (int it = 0; it < 4; ++it) {
            int r = lrow + it * 32;
            ra[it] = *reinterpret_cast<const float4*>(X + (size_t)(p0 + r) * IC + c0 + lc4);
            rb[it] = *reinterpret_cast<const float4*>(W + (size_t)(o0 + r) * IC + c0 + lc4);
        }
    };
    auto stash = [&](int buf) {
        #pragma unroll
        for (int it = 0; it < 4; ++it) {
            int r = lrow + it * 32;
            int ha = buf * TILEH + r * SPAD + lc4;
            uint32_t l0, l1, h0, h1;
            h0 = split2(ra[it].x, ra[it].y, l0);
            h1 = split2(ra[it].z, ra[it].w, l1);
            *reinterpret_cast<uint2*>(&Ahi[ha]) = make_uint2(h0, h1);
            *reinterpret_cast<uint2*>(&Alo[ha]) = make_uint2(l0, l1);
            h0 = split2(rb[it].x, rb[it].y, l0);
            h1 = split2(rb[it].z, rb[it].w, l1);
            *reinterpret_cast<uint2*>(&Bhi[ha]) = make_uint2(h0, h1);
            *reinterpret_cast<uint2*>(&Blo[ha]) = make_uint2(l0, l1);
        }
    };
    auto compute = [&](int buf) {
        #pragma unroll
        for (int k0 = 0; k0 < 32; k0 += 16) {
            uint32_t ah[4][4], al[4][4], bh[4][2], bl[4][2];
            int ab = buf * TILEH + k0 + 2 * t;
            #pragma unroll
            for (int i = 0; i < 4; i++) {
                int base = ab + (wm + i * 16 + g) * SPAD;
                ah[i][0] = *reinterpret_cast<uint32_t*>(&Ahi[base]);
                ah[i][1] = *reinterpret_cast<uint32_t*>(&Ahi[base + 8 * SPAD]);
                ah[i][2] = *reinterpret_cast<uint32_t*>(&Ahi[base + 8]);
                ah[i][3] = *reinterpret_cast<uint32_t*>(&Ahi[base + 8 * SPAD + 8]);
                al[i][0] = *reinterpret_cast<uint32_t*>(&Alo[base]);
                al[i][1] = *reinterpret_cast<uint32_t*>(&Alo[base + 8 * SPAD]);
                al[i][2] = *reinterpret_cast<uint32_t*>(&Alo[base + 8]);
                al[i][3] = *reinterpret_cast<uint32_t*>(&Alo[base + 8 * SPAD + 8]);
            }
            #pragma unroll
            for (int j = 0; j < 4; j++) {
                int base = ab + (wn + j * 8 + g) * SPAD;
                bh[j][0] = *reinterpret_cast<uint32_t*>(&Bhi[base]);
                bh[j][1] = *reinterpret_cast<uint32_t*>(&Bhi[base + 8]);
                bl[j][0] = *reinterpret_cast<uint32_t*>(&Blo[base]);
                bl[j][1] = *reinterpret_cast<uint32_t*>(&Blo[base + 8]);
            }
            #pragma unroll
            for (int i = 0; i < 4; i++)
                #pragma unroll
                for (int j = 0; j < 4; j++) mma16816(acc[i][j], ah[i], bh[j]);
            #pragma unroll
            for (int i = 0; i < 4; i++)
                #pragma unroll
                for (int j = 0; j < 4; j++) mma16816(acc[i][j], ah[i], bl[j]);
            #pragma unroll
            for (int i = 0; i < 4; i++)
                #pragma unroll
                for (int j = 0; j < 4; j++) mma16816(acc[i][j], al[i], bh[j]);
        }
    };

    fetch(0); stash(0);
    __syncthreads();
    const int KT = IC >> 5;
    for (int kt = 0; kt < KT; ++kt) {
        int buf = kt & 1;
        if (kt + 1 < KT) fetch(kt + 1);
        compute(buf);
        if (kt + 1 < KT) stash(buf ^ 1);
        __syncthreads();
    }

    // epilogue
    #pragma unroll
    for (int j = 0; j < 4; j++) {
        int col = o0 + wn + j * 8 + 2 * t;
        float b0 = bias[col], b1 = bias[col + 1];
        #pragma unroll
        for (int i = 0; i < 4; i++) {
            int r0 = p0 + wm + i * 16 + g;
            float v0 = acc[i][j][0] + b0, v1 = acc[i][j][1] + b1;
            float v2 = acc[i][j][2] + b0, v3 = acc[i][j][3] + b1;
            if (gelu) {
                v0 = 0.5f * v0 * (1.f + erff(v0 * 0.70710678118654752f));
                v1 = 0.5f * v1 * (1.f + erff(v1 * 0.70710678118654752f));
                v2 = 0.5f * v2 * (1.f + erff(v2 * 0.70710678118654752f));
                v3 = 0.5f * v3 * (1.f + erff(v3 * 0.70710678118654752f));
            }
            *reinterpret_cast<float2*>(&out[(size_t)r0 * OC + col])       = make_float2(v0, v1);
            *reinterpret_cast<float2*>(&out[(size_t)(r0 + 8) * OC + col]) = make_float2(v2, v3);
        }
    }
}

// ================= relative-position bias =================
__global__ void k_bias(const float* __restrict__ table, float* __restrict__ bias) {
    int i = blockIdx.x * blockDim.x + threadIdx.x;
    if (i >= NHD * NN * NN) return;
    int h = i / (NN * NN);
    int rem = i % (NN * NN);
    int n = rem / NN, k = rem % NN;
    int dr = n / WWIN - k / WWIN + (WWIN - 1);
    int dc = n % WWIN - k % WWIN + (WWIN - 1);
    bias[i] = table[(dr * (2 * WWIN - 1) + dc) * NHD + h];
}

// ================= channel LayerNorm: NCHW in, (pt, C) out =================
template <bool BLOCKED>
__global__ void k_ln(const float* __restrict__ x, const float* __restrict__ w,
                     const float* __restrict__ b, float* __restrict__ out) {
    int blk = blockIdx.x;
    int w0  = (blk & 1) * 28;
    int bh  = blk >> 1;
    int h   = bh % HH;
    int bb  = bh / HH;
    int tx = threadIdx.x, ty = threadIdx.y;
    int wpos = w0 + tx;

    const float* xb = x + (size_t)bb * CC * HWSZ + h * HH + wpos;

    float s = 0.f, s2 = 0.f;
    #pragma unroll
    for (int c = ty; c < CC; c += 8) {
        float v = xb[(size_t)c * HWSZ];
        s += v; s2 += v * v;
    }
    __shared__ float sh_s[8][28], sh_s2[8][28];
    __shared__ float sh_mu[28], sh_rs[28];
    sh_s[ty][tx] = s; sh_s2[ty][tx] = s2;
    __syncthreads();
    if (ty == 0) {
        float ts = 0.f, ts2 = 0.f;
        #pragma unroll
        for (int j = 0; j < 8; j++) { ts += sh_s[j][tx]; ts2 += sh_s2[j][tx]; }
        float mu  = ts * (1.f / CC);
        float var = ts2 * (1.f / CC) - mu * mu;
        sh_mu[tx] = mu; sh_rs[tx] = rsqrtf(var + EPSV);
    }
    __syncthreads();
    float mu = sh_mu[tx], rs = sh_rs[tx];

    size_t pt;
    if (BLOCKED) {
        int m = bb * 64 + (h / WWIN) * 8 + (wpos / WWIN);
        int n = (h % WWIN) * WWIN + (wpos % WWIN);
        pt = (size_t)m * NN + n;
    } else {
        pt = (size_t)bb * HWSZ + h * HH + wpos;
    }
    float* ob = out + pt * CC;
    #pragma unroll
    for (int c = ty; c < CC; c += 8)
        ob[c] = (xb[(size_t)c * HWSZ] - mu) * rs * w[c] + b[c];
}

// ================= attention core per (window, head) =================
#define QPAD 36
__global__ void k_attn(const float* __restrict__ qkv, const float* __restrict__ bias,
                       float* __restrict__ out) {
    int m = blockIdx.x >> 3;
    int h = blockIdx.x & 7;

    __shared__ float sq[NN * QPAD], sk[NN * QPAD], sv[NN * QPAD];
    __shared__ float at[NN * 52];

    int tid = threadIdx.x;
    const float* baseq = qkv + (size_t)(m * NN) * (3 * CC) + h * 32;
    #pragma unroll 2
    for (int i = tid; i < NN * 8; i += 256) {
        int n = i >> 3, d4 = (i & 7) << 2;
        const float* rp = baseq + (size_t)n * (3 * CC);
        float4 q4 = *reinterpret_cast<const float4*>(rp + d4);
        float4 k4 = *reinterpret_cast<const float4*>(rp + CC + d4);
        float4 v4 = *reinterpret_cast<const float4*>(rp + 2 * CC + d4);
        *reinterpret_cast<float4*>(&sq[n * QPAD + d4]) = q4;
        *reinterpret_cast<float4*>(&sk[n * QPAD + d4]) = k4;
        *reinterpret_cast<float4*>(&sv[n * QPAD + d4]) = v4;
    }
    __syncthreads();

    const float* bh = bias + h * NN * NN;
    const float scale = 0.17677669529663687f;  // 32^-0.5
    for (int i = tid; i < NN * NN; i += 256) {
        int n = i / NN, kk = i % NN;
        const float4* qr = reinterpret_cast<const float4*>(&sq[n * QPAD]);
        const float4* kr = reinterpret_cast<const float4*>(&sk[kk * QPAD]);
        float s = 0.f;
        #pragma unroll
        for (int d = 0; d < 8; d++) {
            float4 a = qr[d], b = kr[d];
            s += a.x * b.x + a.y * b.y + a.z * b.z + a.w * b.w;
        }
        at[n * 52 + kk] = s * scale + bh[i];
    }
    __syncthreads();

    int warp = tid >> 5, lane = tid & 31;
    for (int n = warp; n < NN; n += 8) {
        float v0 = at[n * 52 + lane];
        float v1 = (lane + 32 < NN) ? at[n * 52 + lane + 32] : -INFINITY;
        float mx = fmaxf(v0, v1);
        #pragma unroll
        for (int o = 16; o; o >>= 1) mx = fmaxf(mx, __shfl_xor_sync(0xffffffffu, mx, o));
        float e0 = __expf(v0 - mx);
        float e1 = (lane + 32 < NN) ? __expf(v1 - mx) : 0.f;
        float s = e0 + e1;
        #pragma unroll
        for (int o = 16; o; o >>= 1) s += __shfl_xor_sync(0xffffffffu, s, o);
        float inv = 1.f / s;
        at[n * 52 + lane] = e0 * inv;
        if (lane + 32 < NN) at[n * 52 + lane + 32] = e1 * inv;
    }
    __syncthreads();

    for (int i = tid; i < NN * 8; i += 256) {
        int n = i >> 3, d4 = (i & 7) << 2;
        float4 accv = make_float4(0.f, 0.f, 0.f, 0.f);
        #pragma unroll 7
        for (int kk = 0; kk < NN; kk++) {
            float wv = at[n * 52 + kk];
            float4 v4 = *reinterpret_cast<const float4*>(&sv[kk * QPAD + d4]);
            accv.x += wv * v4.x; accv.y += wv * v4.y;
            accv.z += wv * v4.z; accv.w += wv * v4.w;
        }
        *reinterpret_cast<float4*>(&out[(size_t)(m * NN + n) * CC + h * 32 + d4]) = accv;
    }
}

// ================= residuals =================
__global__ void k_resid(const float* __restrict__ x, const float* __restrict__ y,
                        float* __restrict__ out) {
    int i = blockIdx.x * blockDim.x + threadIdx.x;
    if (i >= BB * CC * HWSZ) return;
    int w = i % HH; int t = i / HH;
    int h = t % HH;  t /= HH;
    int c = t % CC;  int b = t / CC;
    int m = b * 64 + (h / WWIN) * 8 + (w / WWIN);
    int n = (h % WWIN) * WWIN + (w % WWIN);
    out[i] = x[i] + y[(size_t)(m * NN + n) * CC + c];
}

__global__ void k_resid2(float* __restrict__ out, const float* __restrict__ z) {
    int i = blockIdx.x * blockDim.x + threadIdx.x;
    if (i >= BB * CC * HWSZ) return;
    int hw = i % HWSZ;
    int c  = (i / HWSZ) % CC;
    int b  = i / (HWSZ * CC);
    out[i] += z[((size_t)b * HWSZ + hw) * CC + c];
}

// ================= host launcher =================
extern "C" void kernel_launch(void* const* d_in, const int* in_sizes, int n_in,
                              void* d_out, int out_size) {
    const float* x      = (const float*)d_in[0];
    const float* ln1_w  = (const float*)d_in[1];
    const float* ln1_b  = (const float*)d_in[2];
    const float* ln2_w  = (const float*)d_in[3];
    const float* ln2_b  = (const float*)d_in[4];
    const float* qkv_w  = (const float*)d_in[5];
    const float* qkv_b  = (const float*)d_in[6];
    const float* proj_w = (const float*)d_in[7];
    const float* proj_b = (const float*)d_in[8];
    const float* table  = (const float*)d_in[9];
    const float* fc1_w  = (const float*)d_in[10];
    const float* fc1_b  = (const float*)d_in[11];
    const float* fc2_w  = (const float*)d_in[12];
    const float* fc2_b  = (const float*)d_in[13];
    float* out = (float*)d_out;

    float *p_xf, *p_qkv, *p_o, *p_y1, *p_bias, *p_ln2, *p_hid;
    cudaGetSymbolAddress((void**)&p_xf,  g_xf);
    cudaGetSymbolAddress((void**)&p_qkv, g_qkv);
    cudaGetSymbolAddress((void**)&p_o,   g_o);
    cudaGetSymbolAddress((void**)&p_y1,  g_y1);
    cudaGetSymbolAddress((void**)&p_bias,g_bias);
    cudaGetSymbolAddress((void**)&p_ln2, g_ln2);
    cudaGetSymbolAddress((void**)&p_hid, g_hid);

    cudaFuncSetAttribute(k_gemm, cudaFuncAttributeMaxDynamicSharedMemorySize, GSMEM);

    k_bias<<<(NHD * NN * NN + 255) / 256, 256>>>(table, p_bias);
    k_ln<true><<<BB * HH * 2, dim3(28, 8)>>>(x, ln1_w, ln1_b, p_xf);

    // attention pass 1
    k_gemm<<<dim3(NPTS / 128, 6), 256, GSMEM>>>(qkv_w, qkv_b, p_xf, p_qkv, CC, 3 * CC, 0);
    k_attn<<<MM * NHD, 256>>>(p_qkv, p_bias, p_o);
    k_gemm<<<dim3(NPTS / 128, 2), 256, GSMEM>>>(proj_w, proj_b, p_o, p_y1, CC, CC, 0);

    // attention pass 2
    k_gemm<<<dim3(NPTS / 128, 6), 256, GSMEM>>>(qkv_w, qkv_b, p_y1, p_qkv, CC, 3 * CC, 0);
    k_attn<<<MM * NHD, 256>>>(p_qkv, p_bias, p_o);
    k_gemm<<<dim3(NPTS / 128, 2), 256, GSMEM>>>(proj_w, proj_b, p_o, p_xf, CC, CC, 0);

    // residual + unblock
    k_resid<<<(BB * CC * HWSZ + 255) / 256, 256>>>(x, p_xf, out);

    // LN2 -> (pt2, C)
    k_ln<false><<<BB * HH * 2, dim3(28, 8)>>>(out, ln2_w, ln2_b, p_ln2);

    // MLP
    k_gemm<<<dim3(NPTS / 128, HID_ / 128), 256, GSMEM>>>(fc1_w, fc1_b, p_ln2, p_hid, CC, HID_, 1);
    k_gemm<<<dim3(NPTS / 128, CC / 128),  256, GSMEM>>>(fc2_w, fc2_b, p_hid, p_o, HID_, CC, 0);
    k_resid2<<<(BB * CC * HWSZ + 255) / 256, 256>>>(out, p_o);
}